// round 5
// baseline (speedup 1.0000x reference)
#include <cuda_runtime.h>

#define NN 50000
#define EE 800000
#define D  128

// ---------------- scratch (static device globals: allowed) ----------------
__device__ float g_h   [(size_t)NN * D];   // pre-scaled messages h' = dinv * (x@W)
__device__ float g_agg1[(size_t)NN * D];   // layer-1 aggregation output
__device__ float g_agg2[(size_t)NN * D];   // layer-2 aggregation output
__device__ float g_dinv[NN];
__device__ int   g_cnt [NN];               // degree histogram / fill counters
__device__ int   g_rowptr[NN + 1];
__device__ int   g_srcs[EE];               // src ids bucketed by dst
__device__ float g_sum  [2][D];
__device__ float g_sumsq[2][D];
__device__ float g_scale[2][D];
__device__ float g_shift[2][D];
__device__ int   g_is64;                   // 1 if edge_index is really int64

// ---------------- dtype probe ----------------
// If edge_index is int64 (values < 2^31), every odd int32 word of the buffer is 0.
// If it is int32, odd words are random dst/src values in [0, N) -> almost surely nonzero.
__global__ void detect_dtype(const int* __restrict__ words, int nwords) {
    __shared__ int s_nz;
    int t = threadIdx.x;
    if (t == 0) s_nz = 0;
    __syncthreads();
    int nz = 0;
    for (int i = 2 * t + 1; i < nwords; i += 2 * blockDim.x)
        nz |= (words[i] != 0);
    if (nz) atomicOr(&s_nz, 1);
    __syncthreads();
    if (t == 0) g_is64 = s_nz ? 0 : 1;
}

__device__ __forceinline__ int edge_at(const void* ei, long long idx, int is64) {
    if (is64) return (int)((const long long*)ei)[idx];
    return ((const int*)ei)[idx];
}

// ---------------- CSR build ----------------
__global__ void zero_all(int n) {
    int i = blockIdx.x * blockDim.x + threadIdx.x;
    if (i < n) g_cnt[i] = 0;
    if (i < D) {
        g_sum[0][i] = 0.f; g_sumsq[0][i] = 0.f;
        g_sum[1][i] = 0.f; g_sumsq[1][i] = 0.f;
    }
}

__global__ void count_deg(const void* __restrict__ ei, int ne, int n) {
    int e = blockIdx.x * blockDim.x + threadIdx.x;
    if (e >= ne) return;
    int is64 = g_is64;
    int d = edge_at(ei, (long long)ne + e, is64);       // dst
    if ((unsigned)d < (unsigned)n) atomicAdd(&g_cnt[d], 1);
}

// single block, 1024 threads: exclusive scan of g_cnt -> g_rowptr, dinv, reset cnt
__global__ void scan_build(int n) {
    __shared__ int tsum[1024];
    int t = threadIdx.x;
    int C = (n + 1023) >> 10;
    int b = t * C, e = min(b + C, n);
    int s = 0;
    for (int i = b; i < e; i++) s += g_cnt[i];
    tsum[t] = s;
    __syncthreads();
    for (int off = 1; off < 1024; off <<= 1) {
        int v = (t >= off) ? tsum[t - off] : 0;
        __syncthreads();
        tsum[t] += v;
        __syncthreads();
    }
    int run = (t == 0) ? 0 : tsum[t - 1];
    for (int i = b; i < e; i++) {
        int c = g_cnt[i];
        g_rowptr[i] = run; run += c;
        g_dinv[i] = rsqrtf((float)(c + 1));   // +1 self-loop
        g_cnt[i] = 0;
    }
    if (t == 1023) g_rowptr[n] = run;
}

__global__ void fill_buckets(const void* __restrict__ ei, int ne, int n) {
    int e = blockIdx.x * blockDim.x + threadIdx.x;
    if (e >= ne) return;
    int is64 = g_is64;
    int s = edge_at(ei, e, is64);                        // src
    int d = edge_at(ei, (long long)ne + e, is64);        // dst
    if ((unsigned)d < (unsigned)n && (unsigned)s < (unsigned)n) {
        int p = g_rowptr[d] + atomicAdd(&g_cnt[d], 1);
        g_srcs[p] = s;
    }
}

// ---------------- GEMM: g_h = dinv[r] * (X @ W); layer-2 fuses BN+PReLU on load ----
template<int LAYER>
__global__ void __launch_bounds__(256, 2)
gemm_kernel(const float* __restrict__ Xext, const float* __restrict__ W,
            const float* __restrict__ alpha, int n)
{
    __shared__ float Xs[16][132];   // padded: kills stride-128 bank conflicts
    __shared__ float Ws[16][128];

    const float* __restrict__ X = (LAYER == 0) ? Xext : g_agg1;
    const float* sc = g_scale[0];
    const float* sh = g_shift[0];

    int tid  = threadIdx.x;
    int row0 = blockIdx.x * 128;
    int tx = tid & 15, ty = tid >> 4;
    float al = (LAYER == 1) ? __ldg(alpha) : 0.f;

    float acc[8][8];
#pragma unroll
    for (int i = 0; i < 8; i++)
#pragma unroll
        for (int j = 0; j < 8; j++) acc[i][j] = 0.f;

    for (int k0 = 0; k0 < D; k0 += 16) {
#pragma unroll
        for (int l = 0; l < 2; l++) {
            int idx = tid + l * 256;            // 512 float4 slots = 128x16 tile
            int r = idx >> 2, c4 = idx & 3;
            int gr = row0 + r;
            float4 v = make_float4(0.f, 0.f, 0.f, 0.f);
            if (gr < n) v = *(const float4*)(X + (size_t)gr * D + k0 + c4 * 4);
            if (LAYER == 1) {
                int c = k0 + c4 * 4;
                float4 s4 = *(const float4*)(sc + c);
                float4 h4 = *(const float4*)(sh + c);
                v.x = fmaf(s4.x, v.x, h4.x); v.x = v.x > 0.f ? v.x : al * v.x;
                v.y = fmaf(s4.y, v.y, h4.y); v.y = v.y > 0.f ? v.y : al * v.y;
                v.z = fmaf(s4.z, v.z, h4.z); v.z = v.z > 0.f ? v.z : al * v.z;
                v.w = fmaf(s4.w, v.w, h4.w); v.w = v.w > 0.f ? v.w : al * v.w;
            }
            Xs[c4 * 4 + 0][r] = v.x; Xs[c4 * 4 + 1][r] = v.y;
            Xs[c4 * 4 + 2][r] = v.z; Xs[c4 * 4 + 3][r] = v.w;
        }
#pragma unroll
        for (int l = 0; l < 2; l++) {
            int idx = tid + l * 256;
            int r = idx >> 5, c4 = idx & 31;
            *(float4*)&Ws[r][c4 * 4] = *(const float4*)(W + (size_t)(k0 + r) * D + c4 * 4);
        }
        __syncthreads();

#pragma unroll
        for (int kk = 0; kk < 16; kk++) {
            float a[8], b[8];
            *(float4*)&a[0] = *(const float4*)&Xs[kk][ty * 8];
            *(float4*)&a[4] = *(const float4*)&Xs[kk][ty * 8 + 4];
            *(float4*)&b[0] = *(const float4*)&Ws[kk][tx * 8];
            *(float4*)&b[4] = *(const float4*)&Ws[kk][tx * 8 + 4];
#pragma unroll
            for (int i = 0; i < 8; i++)
#pragma unroll
                for (int j = 0; j < 8; j++) acc[i][j] = fmaf(a[i], b[j], acc[i][j]);
        }
        __syncthreads();
    }

#pragma unroll
    for (int i = 0; i < 8; i++) {
        int r = row0 + ty * 8 + i;
        if (r < n) {
            float dv = g_dinv[r];
#pragma unroll
            for (int j4 = 0; j4 < 2; j4++) {
                int c = tx * 8 + j4 * 4;
                float4 h4 = make_float4(acc[i][j4 * 4 + 0] * dv, acc[i][j4 * 4 + 1] * dv,
                                        acc[i][j4 * 4 + 2] * dv, acc[i][j4 * 4 + 3] * dv);
                *(float4*)(g_h + (size_t)r * D + c) = h4;
            }
        }
    }
}

// ---------------- CSR gather: warp per node, fused self-loop + bias + BN stats ----
// agg[d] = dinv_d * ( sum_{s in N(d)} h'_s  +  h'_d )  +  bias
template<int LAYER>
__global__ void __launch_bounds__(256)
gather_agg(const float* __restrict__ bias, int n)
{
    int lane = threadIdx.x & 31;
    int warp = (int)((blockIdx.x * blockDim.x + threadIdx.x) >> 5);
    int nwarps = (int)((gridDim.x * blockDim.x) >> 5);
    float* __restrict__ A = (LAYER == 0) ? g_agg1 : g_agg2;
    float* __restrict__ S = g_sum[LAYER];
    float* __restrict__ Q = g_sumsq[LAYER];
    int c = lane * 4;
    float4 b4 = *(const float4*)(bias + c);

    float4 ss = make_float4(0.f, 0.f, 0.f, 0.f);
    float4 qq = make_float4(0.f, 0.f, 0.f, 0.f);

    for (int node = warp; node < n; node += nwarps) {
        int beg = g_rowptr[node], end = g_rowptr[node + 1];
        float4 acc = *(const float4*)(g_h + (size_t)node * D + c);   // self-loop
        int e = beg;
        for (; e + 4 <= end; e += 4) {                               // MLP x4
            int s0 = g_srcs[e], s1 = g_srcs[e + 1], s2 = g_srcs[e + 2], s3 = g_srcs[e + 3];
            float4 v0 = *(const float4*)(g_h + (size_t)s0 * D + c);
            float4 v1 = *(const float4*)(g_h + (size_t)s1 * D + c);
            float4 v2 = *(const float4*)(g_h + (size_t)s2 * D + c);
            float4 v3 = *(const float4*)(g_h + (size_t)s3 * D + c);
            v0.x += v1.x; v0.y += v1.y; v0.z += v1.z; v0.w += v1.w;
            v2.x += v3.x; v2.y += v3.y; v2.z += v3.z; v2.w += v3.w;
            acc.x += v0.x + v2.x; acc.y += v0.y + v2.y;
            acc.z += v0.z + v2.z; acc.w += v0.w + v2.w;
        }
        for (; e < end; e++) {
            int s = g_srcs[e];
            float4 v = *(const float4*)(g_h + (size_t)s * D + c);
            acc.x += v.x; acc.y += v.y; acc.z += v.z; acc.w += v.w;
        }
        float dv = g_dinv[node];
        float4 o = make_float4(fmaf(dv, acc.x, b4.x), fmaf(dv, acc.y, b4.y),
                               fmaf(dv, acc.z, b4.z), fmaf(dv, acc.w, b4.w));
        *(float4*)(A + (size_t)node * D + c) = o;
        ss.x += o.x; ss.y += o.y; ss.z += o.z; ss.w += o.w;
        qq.x = fmaf(o.x, o.x, qq.x); qq.y = fmaf(o.y, o.y, qq.y);
        qq.z = fmaf(o.z, o.z, qq.z); qq.w = fmaf(o.w, o.w, qq.w);
    }
    atomicAdd(S + c + 0, ss.x); atomicAdd(S + c + 1, ss.y);
    atomicAdd(S + c + 2, ss.z); atomicAdd(S + c + 3, ss.w);
    atomicAdd(Q + c + 0, qq.x); atomicAdd(Q + c + 1, qq.y);
    atomicAdd(Q + c + 2, qq.z); atomicAdd(Q + c + 3, qq.w);
}

// ---------------- BN finalize / final apply ----------------
template<int LAYER>
__global__ void bn_finalize(const float* __restrict__ g, const float* __restrict__ be,
                            float inv_n) {
    int c = threadIdx.x;
    float mu  = g_sum[LAYER][c] * inv_n;
    float var = g_sumsq[LAYER][c] * inv_n - mu * mu;   // biased variance (training mode)
    float rs  = rsqrtf(var + 1e-5f);
    float scl = g[c] * rs;
    g_scale[LAYER][c] = scl;
    g_shift[LAYER][c] = be[c] - mu * scl;
}

__global__ void apply_out(const float* __restrict__ alpha, float* __restrict__ out, int n) {
    int i = blockIdx.x * blockDim.x + threadIdx.x;    // one float4 each
    if (i >= n * 32) return;
    int c = (i & 31) * 4;
    float al = __ldg(alpha);
    float4 v  = *(const float4*)(g_agg2 + (size_t)i * 4);
    float4 s4 = *(const float4*)(&g_scale[1][c]);
    float4 h4 = *(const float4*)(&g_shift[1][c]);
    v.x = fmaf(s4.x, v.x, h4.x); v.x = v.x > 0.f ? v.x : al * v.x;
    v.y = fmaf(s4.y, v.y, h4.y); v.y = v.y > 0.f ? v.y : al * v.y;
    v.z = fmaf(s4.z, v.z, h4.z); v.z = v.z > 0.f ? v.z : al * v.z;
    v.w = fmaf(s4.w, v.w, h4.w); v.w = v.w > 0.f ? v.w : al * v.w;
    *(float4*)(out + (size_t)i * 4) = v;
}

// ---------------- launch ----------------
extern "C" void kernel_launch(void* const* d_in, const int* in_sizes, int n_in,
                              void* d_out, int out_size)
{
    const float* x   = (const float*)d_in[0];
    const void*  ei  = d_in[1];
    const float* W1  = (const float*)d_in[2];
    const float* b1  = (const float*)d_in[3];
    const float* g1  = (const float*)d_in[4];
    const float* be1 = (const float*)d_in[5];
    const float* a1  = (const float*)d_in[6];
    const float* W2  = (const float*)d_in[7];
    const float* b2  = (const float*)d_in[8];
    const float* g2  = (const float*)d_in[9];
    const float* be2 = (const float*)d_in[10];
    const float* a2  = (const float*)d_in[11];

    int ne = in_sizes[1] / 2;        // 2*E elements either way
    int n  = in_sizes[0] / D;
    float inv_n = 1.f / (float)n;

    int nb256  = (n + 255) / 256;
    int eb256  = (ne + 255) / 256;
    int gemm_b = (n + 127) / 128;
    int gat_b  = 512;                // 4096 warps, ~12 nodes each
    int out_b  = (n * 32 + 255) / 256;
    int probe_words = (2 * ne < 4096) ? 2 * ne : 4096;

    detect_dtype<<<1, 256>>>((const int*)ei, probe_words);
    zero_all    <<<nb256, 256>>>(n);
    count_deg   <<<eb256, 256>>>(ei, ne, n);
    scan_build  <<<1, 1024>>>(n);
    fill_buckets<<<eb256, 256>>>(ei, ne, n);

    // ---- layer 1 ----
    gemm_kernel<0><<<gemm_b, 256>>>(x, W1, a1, n);
    gather_agg<0> <<<gat_b, 256>>>(b1, n);
    bn_finalize<0><<<1, 128>>>(g1, be1, inv_n);

    // ---- layer 2 (BN+PReLU of layer 1 fused into GEMM load) ----
    gemm_kernel<1><<<gemm_b, 256>>>(nullptr, W2, a1, n);
    gather_agg<1> <<<gat_b, 256>>>(b2, n);
    bn_finalize<1><<<1, 128>>>(g2, be2, inv_n);

    apply_out<<<out_b, 256>>>(a2, (float*)d_out, n);
}

// round 6
// speedup vs baseline: 1.3386x; 1.3386x over previous
#include <cuda_runtime.h>

#define NN 50000
#define EE 800000
#define D  128

// ---------------- scratch (static device globals: allowed) ----------------
__device__ float g_h   [(size_t)NN * D];   // pre-scaled messages h' = dinv * (x@W)
__device__ float g_agg1[(size_t)NN * D];   // layer-1 aggregation output
__device__ float g_agg2[(size_t)NN * D];   // layer-2 aggregation output
__device__ float g_dinv[NN];
__device__ int   g_cnt [NN];               // degree histogram / fill counters
__device__ int   g_rowptr[NN + 1];
__device__ int   g_srcs[EE];               // src ids bucketed by dst
__device__ int   g_tmp [NN];               // intra-block inclusive scan values
__device__ int   g_bsum[64];               // per-block totals
__device__ float g_sum  [2][D];
__device__ float g_sumsq[2][D];
__device__ float g_scale[2][D];
__device__ float g_shift[2][D];
__device__ int   g_is64;                   // 1 if edge_index is really int64

// ---------------- f32x2 packed-FMA helpers (sm_103a) ----------------
#define FMA2(d, a, b, c) \
    asm("fma.rn.f32x2 %0, %1, %2, %3;" : "=l"(d) : "l"(a), "l"(b), "l"(c))
#define PACK2(d, lo, hi) \
    asm("mov.b64 %0, {%1, %2};" : "=l"(d) : "f"(lo), "f"(hi))
#define UNPACK2(lo, hi, v) \
    asm("mov.b64 {%0, %1}, %2;" : "=f"(lo), "=f"(hi) : "l"(v))

// ---------------- dtype probe ----------------
// int64 edge values < 2^31 -> every odd int32 word is 0. int32 -> odd words are
// random node ids, almost surely nonzero somewhere in the first 4096 words.
__global__ void detect_dtype(const int* __restrict__ words, int nwords) {
    __shared__ int s_nz;
    int t = threadIdx.x;
    if (t == 0) s_nz = 0;
    __syncthreads();
    int nz = 0;
    for (int i = 2 * t + 1; i < nwords; i += 2 * blockDim.x)
        nz |= (words[i] != 0);
    if (nz) atomicOr(&s_nz, 1);
    __syncthreads();
    if (t == 0) g_is64 = s_nz ? 0 : 1;
}

__device__ __forceinline__ int edge_at(const void* ei, long long idx, int is64) {
    if (is64) return (int)((const long long*)ei)[idx];
    return ((const int*)ei)[idx];
}

// ---------------- CSR build ----------------
__global__ void zero_all(int n) {
    int i = blockIdx.x * blockDim.x + threadIdx.x;
    if (i < n) g_cnt[i] = 0;
    if (i < D) {
        g_sum[0][i] = 0.f; g_sumsq[0][i] = 0.f;
        g_sum[1][i] = 0.f; g_sumsq[1][i] = 0.f;
    }
}

__global__ void count_deg(const void* __restrict__ ei, int ne, int n) {
    int e = blockIdx.x * blockDim.x + threadIdx.x;
    if (e >= ne) return;
    int is64 = g_is64;
    int d = edge_at(ei, (long long)ne + e, is64);       // dst
    if ((unsigned)d < (unsigned)n) atomicAdd(&g_cnt[d], 1);
}

// --- parallel exclusive scan of g_cnt, 3 phases ---
__global__ void scan_phase1(int n) {            // grid = ceil(n/1024), 1024 thr
    __shared__ int sh[1024];
    int t = threadIdx.x;
    int i = blockIdx.x * 1024 + t;
    int v = (i < n) ? g_cnt[i] : 0;
    sh[t] = v;
    __syncthreads();
#pragma unroll
    for (int off = 1; off < 1024; off <<= 1) {
        int u = (t >= off) ? sh[t - off] : 0;
        __syncthreads();
        sh[t] += u;
        __syncthreads();
    }
    if (i < n) g_tmp[i] = sh[t];                // inclusive within block
    if (t == 1023) g_bsum[blockIdx.x] = sh[1023];
}

__global__ void scan_phase2(int nblk) {         // 1 block, 64 threads
    __shared__ int sh[64];
    int t = threadIdx.x;
    sh[t] = (t < nblk) ? g_bsum[t] : 0;
    __syncthreads();
#pragma unroll
    for (int off = 1; off < 64; off <<= 1) {
        int u = (t >= off) ? sh[t - off] : 0;
        __syncthreads();
        sh[t] += u;
        __syncthreads();
    }
    g_bsum[t] = sh[t];                          // inclusive block prefix
}

__global__ void scan_phase3(int n, int nblk) {  // grid covers n+1 threads
    int i = blockIdx.x * blockDim.x + threadIdx.x;
    if (i > n) return;
    if (i == n) { g_rowptr[n] = g_bsum[nblk - 1]; return; }
    int blk = i >> 10;
    int c = g_cnt[i];
    int excl = g_tmp[i] - c + (blk ? g_bsum[blk - 1] : 0);
    g_rowptr[i] = excl;
    g_dinv[i] = rsqrtf((float)(c + 1));         // +1 self-loop
    g_cnt[i] = 0;
}

__global__ void fill_buckets(const void* __restrict__ ei, int ne, int n) {
    int e = blockIdx.x * blockDim.x + threadIdx.x;
    if (e >= ne) return;
    int is64 = g_is64;
    int s = edge_at(ei, e, is64);                        // src
    int d = edge_at(ei, (long long)ne + e, is64);        // dst
    if ((unsigned)d < (unsigned)n && (unsigned)s < (unsigned)n) {
        int p = g_rowptr[d] + atomicAdd(&g_cnt[d], 1);
        g_srcs[p] = s;
    }
}

// ---------------- GEMM: g_h = dinv[r] * (X @ W); layer-2 fuses BN+PReLU on load ----
// Inner product uses packed fma.rn.f32x2 (2 FMAs/instr on the fp32 pipe).
template<int LAYER>
__global__ void __launch_bounds__(256, 2)
gemm_kernel(const float* __restrict__ Xext, const float* __restrict__ W,
            const float* __restrict__ alpha, int n)
{
    __shared__ float Xs[16][132];   // padded: kills stride-128 bank conflicts
    __shared__ float Ws[16][128];

    const float* __restrict__ X = (LAYER == 0) ? Xext : g_agg1;
    const float* sc = g_scale[0];
    const float* sh = g_shift[0];

    int tid  = threadIdx.x;
    int row0 = blockIdx.x * 128;
    int tx = tid & 15, ty = tid >> 4;
    float al = (LAYER == 1) ? __ldg(alpha) : 0.f;

    unsigned long long acc2[8][4];              // 8 rows x 4 packed col-pairs
    {
        unsigned long long z; PACK2(z, 0.f, 0.f);
#pragma unroll
        for (int i = 0; i < 8; i++)
#pragma unroll
            for (int j = 0; j < 4; j++) acc2[i][j] = z;
    }

    for (int k0 = 0; k0 < D; k0 += 16) {
#pragma unroll
        for (int l = 0; l < 2; l++) {
            int idx = tid + l * 256;            // 512 float4 slots = 128x16 tile
            int r = idx >> 2, c4 = idx & 3;
            int gr = row0 + r;
            float4 v = make_float4(0.f, 0.f, 0.f, 0.f);
            if (gr < n) v = *(const float4*)(X + (size_t)gr * D + k0 + c4 * 4);
            if (LAYER == 1) {
                int c = k0 + c4 * 4;
                float4 s4 = *(const float4*)(sc + c);
                float4 h4 = *(const float4*)(sh + c);
                v.x = fmaf(s4.x, v.x, h4.x); v.x = v.x > 0.f ? v.x : al * v.x;
                v.y = fmaf(s4.y, v.y, h4.y); v.y = v.y > 0.f ? v.y : al * v.y;
                v.z = fmaf(s4.z, v.z, h4.z); v.z = v.z > 0.f ? v.z : al * v.z;
                v.w = fmaf(s4.w, v.w, h4.w); v.w = v.w > 0.f ? v.w : al * v.w;
            }
            Xs[c4 * 4 + 0][r] = v.x; Xs[c4 * 4 + 1][r] = v.y;
            Xs[c4 * 4 + 2][r] = v.z; Xs[c4 * 4 + 3][r] = v.w;
        }
#pragma unroll
        for (int l = 0; l < 2; l++) {
            int idx = tid + l * 256;
            int r = idx >> 5, c4 = idx & 31;
            *(float4*)&Ws[r][c4 * 4] = *(const float4*)(W + (size_t)(k0 + r) * D + c4 * 4);
        }
        __syncthreads();

#pragma unroll
        for (int kk = 0; kk < 16; kk++) {
            float a[8];
            *(float4*)&a[0] = *(const float4*)&Xs[kk][ty * 8];
            *(float4*)&a[4] = *(const float4*)&Xs[kk][ty * 8 + 4];
            unsigned long long a2[8], b2[4];
#pragma unroll
            for (int i = 0; i < 8; i++) PACK2(a2[i], a[i], a[i]);
#pragma unroll
            for (int j = 0; j < 4; j++)
                b2[j] = *(const unsigned long long*)&Ws[kk][tx * 8 + j * 2];
#pragma unroll
            for (int i = 0; i < 8; i++)
#pragma unroll
                for (int j = 0; j < 4; j++)
                    FMA2(acc2[i][j], a2[i], b2[j], acc2[i][j]);
        }
        __syncthreads();
    }

#pragma unroll
    for (int i = 0; i < 8; i++) {
        int r = row0 + ty * 8 + i;
        if (r < n) {
            float dv = g_dinv[r];
#pragma unroll
            for (int j4 = 0; j4 < 2; j4++) {
                float e0, e1, e2, e3;
                UNPACK2(e0, e1, acc2[i][j4 * 2 + 0]);
                UNPACK2(e2, e3, acc2[i][j4 * 2 + 1]);
                int c = tx * 8 + j4 * 4;
                float4 h4 = make_float4(e0 * dv, e1 * dv, e2 * dv, e3 * dv);
                *(float4*)(g_h + (size_t)r * D + c) = h4;
            }
        }
    }
}

// ---------------- CSR gather: warp per node, fused self-loop + bias + BN stats ----
// agg[d] = dinv_d * ( sum_{s in N(d)} h'_s  +  h'_d )  +  bias
template<int LAYER>
__global__ void __launch_bounds__(256)
gather_agg(const float* __restrict__ bias, int n)
{
    int lane = threadIdx.x & 31;
    int warp = (int)((blockIdx.x * blockDim.x + threadIdx.x) >> 5);
    int nwarps = (int)((gridDim.x * blockDim.x) >> 5);
    float* __restrict__ A = (LAYER == 0) ? g_agg1 : g_agg2;
    float* __restrict__ S = g_sum[LAYER];
    float* __restrict__ Q = g_sumsq[LAYER];
    int c = lane * 4;
    float4 b4 = *(const float4*)(bias + c);

    float4 ss = make_float4(0.f, 0.f, 0.f, 0.f);
    float4 qq = make_float4(0.f, 0.f, 0.f, 0.f);

    for (int node = warp; node < n; node += nwarps) {
        int beg = g_rowptr[node], end = g_rowptr[node + 1];
        float4 acc = *(const float4*)(g_h + (size_t)node * D + c);   // self-loop
        int e = beg;
        for (; e + 4 <= end; e += 4) {                               // MLP x4
            int s0 = g_srcs[e], s1 = g_srcs[e + 1], s2 = g_srcs[e + 2], s3 = g_srcs[e + 3];
            float4 v0 = *(const float4*)(g_h + (size_t)s0 * D + c);
            float4 v1 = *(const float4*)(g_h + (size_t)s1 * D + c);
            float4 v2 = *(const float4*)(g_h + (size_t)s2 * D + c);
            float4 v3 = *(const float4*)(g_h + (size_t)s3 * D + c);
            v0.x += v1.x; v0.y += v1.y; v0.z += v1.z; v0.w += v1.w;
            v2.x += v3.x; v2.y += v3.y; v2.z += v3.z; v2.w += v3.w;
            acc.x += v0.x + v2.x; acc.y += v0.y + v2.y;
            acc.z += v0.z + v2.z; acc.w += v0.w + v2.w;
        }
        for (; e < end; e++) {
            int s = g_srcs[e];
            float4 v = *(const float4*)(g_h + (size_t)s * D + c);
            acc.x += v.x; acc.y += v.y; acc.z += v.z; acc.w += v.w;
        }
        float dv = g_dinv[node];
        float4 o = make_float4(fmaf(dv, acc.x, b4.x), fmaf(dv, acc.y, b4.y),
                               fmaf(dv, acc.z, b4.z), fmaf(dv, acc.w, b4.w));
        *(float4*)(A + (size_t)node * D + c) = o;
        ss.x += o.x; ss.y += o.y; ss.z += o.z; ss.w += o.w;
        qq.x = fmaf(o.x, o.x, qq.x); qq.y = fmaf(o.y, o.y, qq.y);
        qq.z = fmaf(o.z, o.z, qq.z); qq.w = fmaf(o.w, o.w, qq.w);
    }
    atomicAdd(S + c + 0, ss.x); atomicAdd(S + c + 1, ss.y);
    atomicAdd(S + c + 2, ss.z); atomicAdd(S + c + 3, ss.w);
    atomicAdd(Q + c + 0, qq.x); atomicAdd(Q + c + 1, qq.y);
    atomicAdd(Q + c + 2, qq.z); atomicAdd(Q + c + 3, qq.w);
}

// ---------------- BN finalize / final apply ----------------
template<int LAYER>
__global__ void bn_finalize(const float* __restrict__ g, const float* __restrict__ be,
                            float inv_n) {
    int c = threadIdx.x;
    float mu  = g_sum[LAYER][c] * inv_n;
    float var = g_sumsq[LAYER][c] * inv_n - mu * mu;   // biased variance (training mode)
    float rs  = rsqrtf(var + 1e-5f);
    float scl = g[c] * rs;
    g_scale[LAYER][c] = scl;
    g_shift[LAYER][c] = be[c] - mu * scl;
}

__global__ void apply_out(const float* __restrict__ alpha, float* __restrict__ out, int n) {
    int i = blockIdx.x * blockDim.x + threadIdx.x;    // one float4 each
    if (i >= n * 32) return;
    int c = (i & 31) * 4;
    float al = __ldg(alpha);
    float4 v  = *(const float4*)(g_agg2 + (size_t)i * 4);
    float4 s4 = *(const float4*)(&g_scale[1][c]);
    float4 h4 = *(const float4*)(&g_shift[1][c]);
    v.x = fmaf(s4.x, v.x, h4.x); v.x = v.x > 0.f ? v.x : al * v.x;
    v.y = fmaf(s4.y, v.y, h4.y); v.y = v.y > 0.f ? v.y : al * v.y;
    v.z = fmaf(s4.z, v.z, h4.z); v.z = v.z > 0.f ? v.z : al * v.z;
    v.w = fmaf(s4.w, v.w, h4.w); v.w = v.w > 0.f ? v.w : al * v.w;
    *(float4*)(out + (size_t)i * 4) = v;
}

// ---------------- launch ----------------
extern "C" void kernel_launch(void* const* d_in, const int* in_sizes, int n_in,
                              void* d_out, int out_size)
{
    const float* x   = (const float*)d_in[0];
    const void*  ei  = d_in[1];
    const float* W1  = (const float*)d_in[2];
    const float* b1  = (const float*)d_in[3];
    const float* g1  = (const float*)d_in[4];
    const float* be1 = (const float*)d_in[5];
    const float* a1  = (const float*)d_in[6];
    const float* W2  = (const float*)d_in[7];
    const float* b2  = (const float*)d_in[8];
    const float* g2  = (const float*)d_in[9];
    const float* be2 = (const float*)d_in[10];
    const float* a2  = (const float*)d_in[11];

    int ne = in_sizes[1] / 2;        // 2*E elements either way
    int n  = in_sizes[0] / D;
    float inv_n = 1.f / (float)n;

    int nb256  = (n + 255) / 256;
    int eb256  = (ne + 255) / 256;
    int gemm_b = (n + 127) / 128;
    int gat_b  = 512;                // 4096 warps, ~12 nodes each
    int out_b  = (n * 32 + 255) / 256;
    int probe_words = (2 * ne < 4096) ? 2 * ne : 4096;
    int nblk1024 = (n + 1023) / 1024;

    detect_dtype<<<1, 256>>>((const int*)ei, probe_words);
    zero_all    <<<nb256, 256>>>(n);
    count_deg   <<<eb256, 256>>>(ei, ne, n);
    scan_phase1 <<<nblk1024, 1024>>>(n);
    scan_phase2 <<<1, 64>>>(nblk1024);
    scan_phase3 <<<(n + 1024) / 1024, 1024>>>(n, nblk1024);
    fill_buckets<<<eb256, 256>>>(ei, ne, n);

    // ---- layer 1 ----
    gemm_kernel<0><<<gemm_b, 256>>>(x, W1, a1, n);
    gather_agg<0> <<<gat_b, 256>>>(b1, n);
    bn_finalize<0><<<1, 128>>>(g1, be1, inv_n);

    // ---- layer 2 (BN+PReLU of layer 1 fused into GEMM load) ----
    gemm_kernel<1><<<gemm_b, 256>>>(nullptr, W2, a1, n);
    gather_agg<1> <<<gat_b, 256>>>(b2, n);
    bn_finalize<1><<<1, 128>>>(g2, be2, inv_n);

    apply_out<<<out_b, 256>>>(a2, (float*)d_out, n);
}

// round 7
// speedup vs baseline: 1.3658x; 1.0203x over previous
#include <cuda_runtime.h>
#include <cuda_fp16.h>

#define NN 50000
#define EE 800000
#define D  128

// ---------------- scratch (static device globals: allowed) ----------------
__device__ __half g_h [(size_t)NN * D];    // pre-scaled messages h' = dinv*(x@W), fp16
__device__ float g_agg1[(size_t)NN * D];   // layer-1 aggregation output (fp32)
__device__ float g_agg2[(size_t)NN * D];   // layer-2 aggregation output (fp32)
__device__ float g_dinv[NN];
__device__ int   g_cnt [NN];               // degree histogram / fill counters
__device__ int   g_rowptr[NN + 1];
__device__ int   g_srcs[EE];               // src ids bucketed by dst
__device__ int   g_tmp [NN];               // intra-block inclusive scan values
__device__ int   g_bsum[64];               // per-block totals
__device__ float g_sum  [2][D];
__device__ float g_sumsq[2][D];
__device__ float g_scale[2][D];
__device__ float g_shift[2][D];
__device__ int   g_is64;                   // 1 if edge_index is really int64

// ---------------- f32x2 packed-FMA helpers (sm_103a) ----------------
#define FMA2(d, a, b, c) \
    asm("fma.rn.f32x2 %0, %1, %2, %3;" : "=l"(d) : "l"(a), "l"(b), "l"(c))
#define PACK2(d, lo, hi) \
    asm("mov.b64 %0, {%1, %2};" : "=l"(d) : "f"(lo), "f"(hi))
#define UNPACK2(lo, hi, v) \
    asm("mov.b64 {%0, %1}, %2;" : "=f"(lo), "=f"(hi) : "l"(v))

// ---------------- dtype probe ----------------
// int64 edge values < 2^31 -> every odd int32 word is 0. int32 -> odd words are
// random node ids, almost surely nonzero somewhere in the first 4096 words.
__global__ void detect_dtype(const int* __restrict__ words, int nwords) {
    __shared__ int s_nz;
    int t = threadIdx.x;
    if (t == 0) s_nz = 0;
    __syncthreads();
    int nz = 0;
    for (int i = 2 * t + 1; i < nwords; i += 2 * blockDim.x)
        nz |= (words[i] != 0);
    if (nz) atomicOr(&s_nz, 1);
    __syncthreads();
    if (t == 0) g_is64 = s_nz ? 0 : 1;
}

__device__ __forceinline__ int edge_at(const void* ei, long long idx, int is64) {
    if (is64) return (int)((const long long*)ei)[idx];
    return ((const int*)ei)[idx];
}

// ---------------- CSR build ----------------
__global__ void zero_all(int n) {
    int i = blockIdx.x * blockDim.x + threadIdx.x;
    if (i < n) g_cnt[i] = 0;
    if (i < D) {
        g_sum[0][i] = 0.f; g_sumsq[0][i] = 0.f;
        g_sum[1][i] = 0.f; g_sumsq[1][i] = 0.f;
    }
}

__global__ void count_deg(const void* __restrict__ ei, int ne, int n) {
    int e = blockIdx.x * blockDim.x + threadIdx.x;
    if (e >= ne) return;
    int is64 = g_is64;
    int d = edge_at(ei, (long long)ne + e, is64);       // dst
    if ((unsigned)d < (unsigned)n) atomicAdd(&g_cnt[d], 1);
}

// --- parallel exclusive scan of g_cnt, 3 phases ---
__global__ void scan_phase1(int n) {            // grid = ceil(n/1024), 1024 thr
    __shared__ int sh[1024];
    int t = threadIdx.x;
    int i = blockIdx.x * 1024 + t;
    int v = (i < n) ? g_cnt[i] : 0;
    sh[t] = v;
    __syncthreads();
#pragma unroll
    for (int off = 1; off < 1024; off <<= 1) {
        int u = (t >= off) ? sh[t - off] : 0;
        __syncthreads();
        sh[t] += u;
        __syncthreads();
    }
    if (i < n) g_tmp[i] = sh[t];                // inclusive within block
    if (t == 1023) g_bsum[blockIdx.x] = sh[1023];
}

__global__ void scan_phase2(int nblk) {         // 1 block, 64 threads
    __shared__ int sh[64];
    int t = threadIdx.x;
    sh[t] = (t < nblk) ? g_bsum[t] : 0;
    __syncthreads();
#pragma unroll
    for (int off = 1; off < 64; off <<= 1) {
        int u = (t >= off) ? sh[t - off] : 0;
        __syncthreads();
        sh[t] += u;
        __syncthreads();
    }
    g_bsum[t] = sh[t];                          // inclusive block prefix
}

__global__ void scan_phase3(int n, int nblk) {  // grid covers n+1 threads
    int i = blockIdx.x * blockDim.x + threadIdx.x;
    if (i > n) return;
    if (i == n) { g_rowptr[n] = g_bsum[nblk - 1]; return; }
    int blk = i >> 10;
    int c = g_cnt[i];
    int excl = g_tmp[i] - c + (blk ? g_bsum[blk - 1] : 0);
    g_rowptr[i] = excl;
    g_dinv[i] = rsqrtf((float)(c + 1));         // +1 self-loop
    g_cnt[i] = 0;
}

__global__ void fill_buckets(const void* __restrict__ ei, int ne, int n) {
    int e = blockIdx.x * blockDim.x + threadIdx.x;
    if (e >= ne) return;
    int is64 = g_is64;
    int s = edge_at(ei, e, is64);                        // src
    int d = edge_at(ei, (long long)ne + e, is64);        // dst
    if ((unsigned)d < (unsigned)n && (unsigned)s < (unsigned)n) {
        int p = g_rowptr[d] + atomicAdd(&g_cnt[d], 1);
        g_srcs[p] = s;
    }
}

// ---------------- GEMM: g_h = fp16( dinv[r] * (X @ W) ); layer-2 fuses BN+PReLU ----
// Inner product uses packed fma.rn.f32x2 (2 FMAs/instr on the fp32 pipe).
template<int LAYER>
__global__ void __launch_bounds__(256, 2)
gemm_kernel(const float* __restrict__ Xext, const float* __restrict__ W,
            const float* __restrict__ alpha, int n)
{
    __shared__ float Xs[16][132];   // padded: kills stride-128 bank conflicts
    __shared__ float Ws[16][128];

    const float* __restrict__ X = (LAYER == 0) ? Xext : g_agg1;
    const float* sc = g_scale[0];
    const float* sh = g_shift[0];

    int tid  = threadIdx.x;
    int row0 = blockIdx.x * 128;
    int tx = tid & 15, ty = tid >> 4;
    float al = (LAYER == 1) ? __ldg(alpha) : 0.f;

    unsigned long long acc2[8][4];              // 8 rows x 4 packed col-pairs
    {
        unsigned long long z; PACK2(z, 0.f, 0.f);
#pragma unroll
        for (int i = 0; i < 8; i++)
#pragma unroll
            for (int j = 0; j < 4; j++) acc2[i][j] = z;
    }

    for (int k0 = 0; k0 < D; k0 += 16) {
#pragma unroll
        for (int l = 0; l < 2; l++) {
            int idx = tid + l * 256;            // 512 float4 slots = 128x16 tile
            int r = idx >> 2, c4 = idx & 3;
            int gr = row0 + r;
            float4 v = make_float4(0.f, 0.f, 0.f, 0.f);
            if (gr < n) v = *(const float4*)(X + (size_t)gr * D + k0 + c4 * 4);
            if (LAYER == 1) {
                int c = k0 + c4 * 4;
                float4 s4 = *(const float4*)(sc + c);
                float4 h4 = *(const float4*)(sh + c);
                v.x = fmaf(s4.x, v.x, h4.x); v.x = v.x > 0.f ? v.x : al * v.x;
                v.y = fmaf(s4.y, v.y, h4.y); v.y = v.y > 0.f ? v.y : al * v.y;
                v.z = fmaf(s4.z, v.z, h4.z); v.z = v.z > 0.f ? v.z : al * v.z;
                v.w = fmaf(s4.w, v.w, h4.w); v.w = v.w > 0.f ? v.w : al * v.w;
            }
            Xs[c4 * 4 + 0][r] = v.x; Xs[c4 * 4 + 1][r] = v.y;
            Xs[c4 * 4 + 2][r] = v.z; Xs[c4 * 4 + 3][r] = v.w;
        }
#pragma unroll
        for (int l = 0; l < 2; l++) {
            int idx = tid + l * 256;
            int r = idx >> 5, c4 = idx & 31;
            *(float4*)&Ws[r][c4 * 4] = *(const float4*)(W + (size_t)(k0 + r) * D + c4 * 4);
        }
        __syncthreads();

#pragma unroll
        for (int kk = 0; kk < 16; kk++) {
            float a[8];
            *(float4*)&a[0] = *(const float4*)&Xs[kk][ty * 8];
            *(float4*)&a[4] = *(const float4*)&Xs[kk][ty * 8 + 4];
            unsigned long long a2[8], b2[4];
#pragma unroll
            for (int i = 0; i < 8; i++) PACK2(a2[i], a[i], a[i]);
#pragma unroll
            for (int j = 0; j < 4; j++)
                b2[j] = *(const unsigned long long*)&Ws[kk][tx * 8 + j * 2];
#pragma unroll
            for (int i = 0; i < 8; i++)
#pragma unroll
                for (int j = 0; j < 4; j++)
                    FMA2(acc2[i][j], a2[i], b2[j], acc2[i][j]);
        }
        __syncthreads();
    }

    // epilogue: scale by dinv, convert to fp16, one 16B store of 8 halves per row
#pragma unroll
    for (int i = 0; i < 8; i++) {
        int r = row0 + ty * 8 + i;
        if (r < n) {
            float dv = g_dinv[r];
            float e[8];
#pragma unroll
            for (int j = 0; j < 4; j++) {
                float lo, hi;
                UNPACK2(lo, hi, acc2[i][j]);
                e[j * 2 + 0] = lo * dv;
                e[j * 2 + 1] = hi * dv;
            }
            __half2 p[4];
#pragma unroll
            for (int j = 0; j < 4; j++)
                p[j] = __floats2half2_rn(e[j * 2], e[j * 2 + 1]);
            *(uint4*)(g_h + (size_t)r * D + tx * 8) = *(uint4*)p;
        }
    }
}

// ---------------- CSR gather: warp per node, fp16 messages, fp32 accumulate ----
// agg[d] = dinv_d * ( sum_{s in N(d)} h'_s  +  h'_d )  +  bias
template<int LAYER>
__global__ void __launch_bounds__(256)
gather_agg(const float* __restrict__ bias, int n)
{
    int lane = threadIdx.x & 31;
    int warp = (int)((blockIdx.x * blockDim.x + threadIdx.x) >> 5);
    int nwarps = (int)((gridDim.x * blockDim.x) >> 5);
    float* __restrict__ A = (LAYER == 0) ? g_agg1 : g_agg2;
    float* __restrict__ S = g_sum[LAYER];
    float* __restrict__ Q = g_sumsq[LAYER];
    int c = lane * 4;                           // each lane: 4 columns = 2 half2 = 8 B
    float4 b4 = *(const float4*)(bias + c);

    float4 ss = make_float4(0.f, 0.f, 0.f, 0.f);
    float4 qq = make_float4(0.f, 0.f, 0.f, 0.f);

    for (int node = warp; node < n; node += nwarps) {
        int beg = g_rowptr[node], end = g_rowptr[node + 1];
        // self-loop
        float4 acc;
        {
            uint2 u = *(const uint2*)(g_h + (size_t)node * D + c);
            float2 f0 = __half22float2(*(__half2*)&u.x);
            float2 f1 = __half22float2(*(__half2*)&u.y);
            acc = make_float4(f0.x, f0.y, f1.x, f1.y);
        }
        int e = beg;
        for (; e + 4 <= end; e += 4) {                               // MLP x4
            int s0 = g_srcs[e], s1 = g_srcs[e + 1], s2 = g_srcs[e + 2], s3 = g_srcs[e + 3];
            uint2 u0 = *(const uint2*)(g_h + (size_t)s0 * D + c);
            uint2 u1 = *(const uint2*)(g_h + (size_t)s1 * D + c);
            uint2 u2 = *(const uint2*)(g_h + (size_t)s2 * D + c);
            uint2 u3 = *(const uint2*)(g_h + (size_t)s3 * D + c);
            float2 a0 = __half22float2(*(__half2*)&u0.x), a1 = __half22float2(*(__half2*)&u0.y);
            float2 b0 = __half22float2(*(__half2*)&u1.x), b1 = __half22float2(*(__half2*)&u1.y);
            float2 c0 = __half22float2(*(__half2*)&u2.x), c1 = __half22float2(*(__half2*)&u2.y);
            float2 d0 = __half22float2(*(__half2*)&u3.x), d1 = __half22float2(*(__half2*)&u3.y);
            acc.x += (a0.x + b0.x) + (c0.x + d0.x);
            acc.y += (a0.y + b0.y) + (c0.y + d0.y);
            acc.z += (a1.x + b1.x) + (c1.x + d1.x);
            acc.w += (a1.y + b1.y) + (c1.y + d1.y);
        }
        for (; e < end; e++) {
            int s = g_srcs[e];
            uint2 u = *(const uint2*)(g_h + (size_t)s * D + c);
            float2 f0 = __half22float2(*(__half2*)&u.x);
            float2 f1 = __half22float2(*(__half2*)&u.y);
            acc.x += f0.x; acc.y += f0.y; acc.z += f1.x; acc.w += f1.y;
        }
        float dv = g_dinv[node];
        float4 o = make_float4(fmaf(dv, acc.x, b4.x), fmaf(dv, acc.y, b4.y),
                               fmaf(dv, acc.z, b4.z), fmaf(dv, acc.w, b4.w));
        *(float4*)(A + (size_t)node * D + c) = o;
        ss.x += o.x; ss.y += o.y; ss.z += o.z; ss.w += o.w;
        qq.x = fmaf(o.x, o.x, qq.x); qq.y = fmaf(o.y, o.y, qq.y);
        qq.z = fmaf(o.z, o.z, qq.z); qq.w = fmaf(o.w, o.w, qq.w);
    }
    atomicAdd(S + c + 0, ss.x); atomicAdd(S + c + 1, ss.y);
    atomicAdd(S + c + 2, ss.z); atomicAdd(S + c + 3, ss.w);
    atomicAdd(Q + c + 0, qq.x); atomicAdd(Q + c + 1, qq.y);
    atomicAdd(Q + c + 2, qq.z); atomicAdd(Q + c + 3, qq.w);
}

// ---------------- BN finalize / final apply ----------------
template<int LAYER>
__global__ void bn_finalize(const float* __restrict__ g, const float* __restrict__ be,
                            float inv_n) {
    int c = threadIdx.x;
    float mu  = g_sum[LAYER][c] * inv_n;
    float var = g_sumsq[LAYER][c] * inv_n - mu * mu;   // biased variance (training mode)
    float rs  = rsqrtf(var + 1e-5f);
    float scl = g[c] * rs;
    g_scale[LAYER][c] = scl;
    g_shift[LAYER][c] = be[c] - mu * scl;
}

__global__ void apply_out(const float* __restrict__ alpha, float* __restrict__ out, int n) {
    int i = blockIdx.x * blockDim.x + threadIdx.x;    // one float4 each
    if (i >= n * 32) return;
    int c = (i & 31) * 4;
    float al = __ldg(alpha);
    float4 v  = *(const float4*)(g_agg2 + (size_t)i * 4);
    float4 s4 = *(const float4*)(&g_scale[1][c]);
    float4 h4 = *(const float4*)(&g_shift[1][c]);
    v.x = fmaf(s4.x, v.x, h4.x); v.x = v.x > 0.f ? v.x : al * v.x;
    v.y = fmaf(s4.y, v.y, h4.y); v.y = v.y > 0.f ? v.y : al * v.y;
    v.z = fmaf(s4.z, v.z, h4.z); v.z = v.z > 0.f ? v.z : al * v.z;
    v.w = fmaf(s4.w, v.w, h4.w); v.w = v.w > 0.f ? v.w : al * v.w;
    *(float4*)(out + (size_t)i * 4) = v;
}

// ---------------- launch ----------------
extern "C" void kernel_launch(void* const* d_in, const int* in_sizes, int n_in,
                              void* d_out, int out_size)
{
    const float* x   = (const float*)d_in[0];
    const void*  ei  = d_in[1];
    const float* W1  = (const float*)d_in[2];
    const float* b1  = (const float*)d_in[3];
    const float* g1  = (const float*)d_in[4];
    const float* be1 = (const float*)d_in[5];
    const float* a1  = (const float*)d_in[6];
    const float* W2  = (const float*)d_in[7];
    const float* b2  = (const float*)d_in[8];
    const float* g2  = (const float*)d_in[9];
    const float* be2 = (const float*)d_in[10];
    const float* a2  = (const float*)d_in[11];

    int ne = in_sizes[1] / 2;        // 2*E elements either way
    int n  = in_sizes[0] / D;
    float inv_n = 1.f / (float)n;

    int nb256  = (n + 255) / 256;
    int eb256  = (ne + 255) / 256;
    int gemm_b = (n + 127) / 128;
    int gat_b  = 512;                // 4096 warps, ~12 nodes each
    int out_b  = (n * 32 + 255) / 256;
    int probe_words = (2 * ne < 4096) ? 2 * ne : 4096;
    int nblk1024 = (n + 1023) / 1024;

    detect_dtype<<<1, 256>>>((const int*)ei, probe_words);
    zero_all    <<<nb256, 256>>>(n);
    count_deg   <<<eb256, 256>>>(ei, ne, n);
    scan_phase1 <<<nblk1024, 1024>>>(n);
    scan_phase2 <<<1, 64>>>(nblk1024);
    scan_phase3 <<<(n + 1024) / 1024, 1024>>>(n, nblk1024);
    fill_buckets<<<eb256, 256>>>(ei, ne, n);

    // ---- layer 1 ----
    gemm_kernel<0><<<gemm_b, 256>>>(x, W1, a1, n);
    gather_agg<0> <<<gat_b, 256>>>(b1, n);
    bn_finalize<0><<<1, 128>>>(g1, be1, inv_n);

    // ---- layer 2 (BN+PReLU of layer 1 fused into GEMM load) ----
    gemm_kernel<1><<<gemm_b, 256>>>(nullptr, W2, a1, n);
    gather_agg<1> <<<gat_b, 256>>>(b2, n);
    bn_finalize<1><<<1, 128>>>(g2, be2, inv_n);

    apply_out<<<out_b, 256>>>(a2, (float*)d_out, n);
}

// round 8
// speedup vs baseline: 1.7272x; 1.2647x over previous
#include <cuda_runtime.h>
#include <cuda_fp16.h>

#define NN 50000
#define EE 800000
#define D  128

// ---------------- scratch (static device globals: allowed) ----------------
__device__ __half g_h [(size_t)NN * D];    // pre-scaled messages h' = dinv*(x@W), fp16
__device__ float g_agg1[(size_t)NN * D];   // layer-1 aggregation output (fp32)
__device__ float g_agg2[(size_t)NN * D];   // layer-2 aggregation output (fp32)
__device__ float g_dinv[NN];
__device__ int   g_cnt [NN];               // degree histogram / fill counters
__device__ int   g_rowptr[NN + 1];
__device__ int   g_srcs[EE];               // src ids bucketed by dst
__device__ int   g_tmp [NN];               // intra-block inclusive scan values
__device__ int   g_bsum[64];               // per-block totals
__device__ float g_sum  [2][D];
__device__ float g_sumsq[2][D];
__device__ float g_scale[2][D];
__device__ float g_shift[2][D];
__device__ int   g_is64;                   // 1 if edge_index is really int64

// ---------------- f32x2 packed-FMA helpers (sm_103a) ----------------
#define FMA2(d, a, b, c) \
    asm("fma.rn.f32x2 %0, %1, %2, %3;" : "=l"(d) : "l"(a), "l"(b), "l"(c))
#define PACK2(d, lo, hi) \
    asm("mov.b64 %0, {%1, %2};" : "=l"(d) : "f"(lo), "f"(hi))
#define UNPACK2(lo, hi, v) \
    asm("mov.b64 {%0, %1}, %2;" : "=f"(lo), "=f"(hi) : "l"(v))

// ---------------- dtype probe ----------------
__global__ void detect_dtype(const int* __restrict__ words, int nwords) {
    __shared__ int s_nz;
    int t = threadIdx.x;
    if (t == 0) s_nz = 0;
    __syncthreads();
    int nz = 0;
    for (int i = 2 * t + 1; i < nwords; i += 2 * blockDim.x)
        nz |= (words[i] != 0);
    if (nz) atomicOr(&s_nz, 1);
    __syncthreads();
    if (t == 0) g_is64 = s_nz ? 0 : 1;
}

__device__ __forceinline__ int edge_at(const void* ei, long long idx, int is64) {
    if (is64) return (int)((const long long*)ei)[idx];
    return ((const int*)ei)[idx];
}

// ---------------- CSR build ----------------
__global__ void zero_all(int n) {
    int i = blockIdx.x * blockDim.x + threadIdx.x;
    if (i < n) g_cnt[i] = 0;
    if (i < D) {
        g_sum[0][i] = 0.f; g_sumsq[0][i] = 0.f;
        g_sum[1][i] = 0.f; g_sumsq[1][i] = 0.f;
    }
}

__global__ void count_deg(const void* __restrict__ ei, int ne, int n) {
    int e = blockIdx.x * blockDim.x + threadIdx.x;
    if (e >= ne) return;
    int is64 = g_is64;
    int d = edge_at(ei, (long long)ne + e, is64);       // dst
    if ((unsigned)d < (unsigned)n) atomicAdd(&g_cnt[d], 1);
}

__global__ void scan_phase1(int n) {            // grid = ceil(n/1024), 1024 thr
    __shared__ int sh[1024];
    int t = threadIdx.x;
    int i = blockIdx.x * 1024 + t;
    int v = (i < n) ? g_cnt[i] : 0;
    sh[t] = v;
    __syncthreads();
#pragma unroll
    for (int off = 1; off < 1024; off <<= 1) {
        int u = (t >= off) ? sh[t - off] : 0;
        __syncthreads();
        sh[t] += u;
        __syncthreads();
    }
    if (i < n) g_tmp[i] = sh[t];                // inclusive within block
    if (t == 1023) g_bsum[blockIdx.x] = sh[1023];
}

__global__ void scan_phase2(int nblk) {         // 1 block, 64 threads
    __shared__ int sh[64];
    int t = threadIdx.x;
    sh[t] = (t < nblk) ? g_bsum[t] : 0;
    __syncthreads();
#pragma unroll
    for (int off = 1; off < 64; off <<= 1) {
        int u = (t >= off) ? sh[t - off] : 0;
        __syncthreads();
        sh[t] += u;
        __syncthreads();
    }
    g_bsum[t] = sh[t];                          // inclusive block prefix
}

__global__ void scan_phase3(int n, int nblk) {  // grid covers n+1 threads
    int i = blockIdx.x * blockDim.x + threadIdx.x;
    if (i > n) return;
    if (i == n) { g_rowptr[n] = g_bsum[nblk - 1]; return; }
    int blk = i >> 10;
    int c = g_cnt[i];
    int excl = g_tmp[i] - c + (blk ? g_bsum[blk - 1] : 0);
    g_rowptr[i] = excl;
    g_dinv[i] = rsqrtf((float)(c + 1));         // +1 self-loop
    g_cnt[i] = 0;
}

__global__ void fill_buckets(const void* __restrict__ ei, int ne, int n) {
    int e = blockIdx.x * blockDim.x + threadIdx.x;
    if (e >= ne) return;
    int is64 = g_is64;
    int s = edge_at(ei, e, is64);                        // src
    int d = edge_at(ei, (long long)ne + e, is64);        // dst
    if ((unsigned)d < (unsigned)n && (unsigned)s < (unsigned)n) {
        int p = g_rowptr[d] + atomicAdd(&g_cnt[d], 1);
        g_srcs[p] = s;
    }
}

// ---------------- GEMM: g_h = fp16( dinv[r] * (X @ W) ); layer-2 fuses BN+PReLU ----
template<int LAYER>
__global__ void __launch_bounds__(256, 2)
gemm_kernel(const float* __restrict__ Xext, const float* __restrict__ W,
            const float* __restrict__ alpha, int n)
{
    __shared__ float Xs[16][132];   // padded: kills stride-128 bank conflicts
    __shared__ float Ws[16][128];

    const float* __restrict__ X = (LAYER == 0) ? Xext : g_agg1;
    const float* sc = g_scale[0];
    const float* sh = g_shift[0];

    int tid  = threadIdx.x;
    int row0 = blockIdx.x * 128;
    int tx = tid & 15, ty = tid >> 4;
    float al = (LAYER == 1) ? __ldg(alpha) : 0.f;

    unsigned long long acc2[8][4];              // 8 rows x 4 packed col-pairs
    {
        unsigned long long z; PACK2(z, 0.f, 0.f);
#pragma unroll
        for (int i = 0; i < 8; i++)
#pragma unroll
            for (int j = 0; j < 4; j++) acc2[i][j] = z;
    }

    for (int k0 = 0; k0 < D; k0 += 16) {
#pragma unroll
        for (int l = 0; l < 2; l++) {
            int idx = tid + l * 256;            // 512 float4 slots = 128x16 tile
            int r = idx >> 2, c4 = idx & 3;
            int gr = row0 + r;
            float4 v = make_float4(0.f, 0.f, 0.f, 0.f);
            if (gr < n) v = *(const float4*)(X + (size_t)gr * D + k0 + c4 * 4);
            if (LAYER == 1) {
                int c = k0 + c4 * 4;
                float4 s4 = *(const float4*)(sc + c);
                float4 h4 = *(const float4*)(sh + c);
                v.x = fmaf(s4.x, v.x, h4.x); v.x = v.x > 0.f ? v.x : al * v.x;
                v.y = fmaf(s4.y, v.y, h4.y); v.y = v.y > 0.f ? v.y : al * v.y;
                v.z = fmaf(s4.z, v.z, h4.z); v.z = v.z > 0.f ? v.z : al * v.z;
                v.w = fmaf(s4.w, v.w, h4.w); v.w = v.w > 0.f ? v.w : al * v.w;
            }
            Xs[c4 * 4 + 0][r] = v.x; Xs[c4 * 4 + 1][r] = v.y;
            Xs[c4 * 4 + 2][r] = v.z; Xs[c4 * 4 + 3][r] = v.w;
        }
#pragma unroll
        for (int l = 0; l < 2; l++) {
            int idx = tid + l * 256;
            int r = idx >> 5, c4 = idx & 31;
            *(float4*)&Ws[r][c4 * 4] = *(const float4*)(W + (size_t)(k0 + r) * D + c4 * 4);
        }
        __syncthreads();

#pragma unroll
        for (int kk = 0; kk < 16; kk++) {
            float a[8];
            *(float4*)&a[0] = *(const float4*)&Xs[kk][ty * 8];
            *(float4*)&a[4] = *(const float4*)&Xs[kk][ty * 8 + 4];
            unsigned long long a2[8], b2[4];
#pragma unroll
            for (int i = 0; i < 8; i++) PACK2(a2[i], a[i], a[i]);
#pragma unroll
            for (int j = 0; j < 4; j++)
                b2[j] = *(const unsigned long long*)&Ws[kk][tx * 8 + j * 2];
#pragma unroll
            for (int i = 0; i < 8; i++)
#pragma unroll
                for (int j = 0; j < 4; j++)
                    FMA2(acc2[i][j], a2[i], b2[j], acc2[i][j]);
        }
        __syncthreads();
    }

    // epilogue: scale by dinv, convert to fp16, one 16B store of 8 halves per row
#pragma unroll
    for (int i = 0; i < 8; i++) {
        int r = row0 + ty * 8 + i;
        if (r < n) {
            float dv = g_dinv[r];
            float e[8];
#pragma unroll
            for (int j = 0; j < 4; j++) {
                float lo, hi;
                UNPACK2(lo, hi, acc2[i][j]);
                e[j * 2 + 0] = lo * dv;
                e[j * 2 + 1] = hi * dv;
            }
            __half2 p[4];
#pragma unroll
            for (int j = 0; j < 4; j++)
                p[j] = __floats2half2_rn(e[j * 2], e[j * 2 + 1]);
            *(uint4*)(g_h + (size_t)r * D + tx * 8) = *(uint4*)p;
        }
    }
}

// ---------------- CSR gather: warp per (node, half-row), deep-MLP fp16 gather ----
// Work item = (node, half). Lane covers 2 columns (one half2 = 4 B).
// agg[d] = dinv_d * ( sum_{s in N(d)} h'_s  +  h'_d )  +  bias
template<int LAYER>
__global__ void __launch_bounds__(256)
gather_agg(const float* __restrict__ bias, int n)
{
    int lane = threadIdx.x & 31;
    int warp = (int)((blockIdx.x * blockDim.x + threadIdx.x) >> 5);
    int nwarps = (int)((gridDim.x * blockDim.x) >> 5);
    float* __restrict__ A = (LAYER == 0) ? g_agg1 : g_agg2;
    float* __restrict__ S = g_sum[LAYER];
    float* __restrict__ Q = g_sumsq[LAYER];

    int nitems = 2 * n;
    float2 ss = make_float2(0.f, 0.f);
    float2 qq = make_float2(0.f, 0.f);
    int last_c = 0;

    for (int item = warp; item < nitems; item += nwarps) {
        int node = item >> 1;
        int c = ((item & 1) << 6) + lane * 2;       // column pair
        last_c = c;
        int beg = g_rowptr[node], end = g_rowptr[node + 1];
        const __half* __restrict__ H = g_h + c;

        // self-loop
        float2 acc = __half22float2(*(const __half2*)(H + (size_t)node * D));

        int e = beg;
        for (; e + 8 <= end; e += 8) {              // MLP x8, coalesced idx fetch
            int sv = g_srcs[e + (lane & 7)];        // 8 useful lanes, coalesced 32B
            int s0 = __shfl_sync(0xffffffffu, sv, 0);
            int s1 = __shfl_sync(0xffffffffu, sv, 1);
            int s2 = __shfl_sync(0xffffffffu, sv, 2);
            int s3 = __shfl_sync(0xffffffffu, sv, 3);
            int s4 = __shfl_sync(0xffffffffu, sv, 4);
            int s5 = __shfl_sync(0xffffffffu, sv, 5);
            int s6 = __shfl_sync(0xffffffffu, sv, 6);
            int s7 = __shfl_sync(0xffffffffu, sv, 7);
            __half2 u0 = *(const __half2*)(H + (size_t)s0 * D);
            __half2 u1 = *(const __half2*)(H + (size_t)s1 * D);
            __half2 u2 = *(const __half2*)(H + (size_t)s2 * D);
            __half2 u3 = *(const __half2*)(H + (size_t)s3 * D);
            __half2 u4 = *(const __half2*)(H + (size_t)s4 * D);
            __half2 u5 = *(const __half2*)(H + (size_t)s5 * D);
            __half2 u6 = *(const __half2*)(H + (size_t)s6 * D);
            __half2 u7 = *(const __half2*)(H + (size_t)s7 * D);
            float2 f0 = __half22float2(u0), f1 = __half22float2(u1);
            float2 f2 = __half22float2(u2), f3 = __half22float2(u3);
            float2 f4 = __half22float2(u4), f5 = __half22float2(u5);
            float2 f6 = __half22float2(u6), f7 = __half22float2(u7);
            acc.x += ((f0.x + f1.x) + (f2.x + f3.x)) + ((f4.x + f5.x) + (f6.x + f7.x));
            acc.y += ((f0.y + f1.y) + (f2.y + f3.y)) + ((f4.y + f5.y) + (f6.y + f7.y));
        }
        for (; e < end; e++) {
            int s = g_srcs[e];
            float2 f = __half22float2(*(const __half2*)(H + (size_t)s * D));
            acc.x += f.x; acc.y += f.y;
        }
        float dv = g_dinv[node];
        float bx = bias[c], by = bias[c + 1];
        float ox = fmaf(dv, acc.x, bx);
        float oy = fmaf(dv, acc.y, by);
        *(float2*)(A + (size_t)node * D + c) = make_float2(ox, oy);
        ss.x += ox; ss.y += oy;
        qq.x = fmaf(ox, ox, qq.x); qq.y = fmaf(oy, oy, qq.y);
    }
    // per-lane column pair is constant across items processed by this thread
    atomicAdd(S + last_c + 0, ss.x); atomicAdd(S + last_c + 1, ss.y);
    atomicAdd(Q + last_c + 0, qq.x); atomicAdd(Q + last_c + 1, qq.y);
}

// ---------------- BN finalize / final apply ----------------
template<int LAYER>
__global__ void bn_finalize(const float* __restrict__ g, const float* __restrict__ be,
                            float inv_n) {
    int c = threadIdx.x;
    float mu  = g_sum[LAYER][c] * inv_n;
    float var = g_sumsq[LAYER][c] * inv_n - mu * mu;   // biased variance (training mode)
    float rs  = rsqrtf(var + 1e-5f);
    float scl = g[c] * rs;
    g_scale[LAYER][c] = scl;
    g_shift[LAYER][c] = be[c] - mu * scl;
}

__global__ void apply_out(const float* __restrict__ alpha, float* __restrict__ out, int n) {
    int i = blockIdx.x * blockDim.x + threadIdx.x;    // one float4 each
    if (i >= n * 32) return;
    int c = (i & 31) * 4;
    float al = __ldg(alpha);
    float4 v  = *(const float4*)(g_agg2 + (size_t)i * 4);
    float4 s4 = *(const float4*)(&g_scale[1][c]);
    float4 h4 = *(const float4*)(&g_shift[1][c]);
    v.x = fmaf(s4.x, v.x, h4.x); v.x = v.x > 0.f ? v.x : al * v.x;
    v.y = fmaf(s4.y, v.y, h4.y); v.y = v.y > 0.f ? v.y : al * v.y;
    v.z = fmaf(s4.z, v.z, h4.z); v.z = v.z > 0.f ? v.z : al * v.z;
    v.w = fmaf(s4.w, v.w, h4.w); v.w = v.w > 0.f ? v.w : al * v.w;
    *(float4*)(out + (size_t)i * 4) = v;
}

// ---------------- launch ----------------
extern "C" void kernel_launch(void* const* d_in, const int* in_sizes, int n_in,
                              void* d_out, int out_size)
{
    const float* x   = (const float*)d_in[0];
    const void*  ei  = d_in[1];
    const float* W1  = (const float*)d_in[2];
    const float* b1  = (const float*)d_in[3];
    const float* g1  = (const float*)d_in[4];
    const float* be1 = (const float*)d_in[5];
    const float* a1  = (const float*)d_in[6];
    const float* W2  = (const float*)d_in[7];
    const float* b2  = (const float*)d_in[8];
    const float* g2  = (const float*)d_in[9];
    const float* be2 = (const float*)d_in[10];
    const float* a2  = (const float*)d_in[11];

    int ne = in_sizes[1] / 2;        // 2*E elements either way
    int n  = in_sizes[0] / D;
    float inv_n = 1.f / (float)n;

    int nb256  = (n + 255) / 256;
    int eb256  = (ne + 255) / 256;
    int gemm_b = (n + 127) / 128;
    int gat_b  = 1184;               // ~full residency: 148 SMs x 8 blocks
    int out_b  = (n * 32 + 255) / 256;
    int probe_words = (2 * ne < 4096) ? 2 * ne : 4096;
    int nblk1024 = (n + 1023) / 1024;

    detect_dtype<<<1, 256>>>((const int*)ei, probe_words);
    zero_all    <<<nb256, 256>>>(n);
    count_deg   <<<eb256, 256>>>(ei, ne, n);
    scan_phase1 <<<nblk1024, 1024>>>(n);
    scan_phase2 <<<1, 64>>>(nblk1024);
    scan_phase3 <<<(n + 1024) / 1024, 1024>>>(n, nblk1024);
    fill_buckets<<<eb256, 256>>>(ei, ne, n);

    // ---- layer 1 ----
    gemm_kernel<0><<<gemm_b, 256>>>(x, W1, a1, n);
    gather_agg<0> <<<gat_b, 256>>>(b1, n);
    bn_finalize<0><<<1, 128>>>(g1, be1, inv_n);

    // ---- layer 2 (BN+PReLU of layer 1 fused into GEMM load) ----
    gemm_kernel<1><<<gemm_b, 256>>>(nullptr, W2, a1, n);
    gather_agg<1> <<<gat_b, 256>>>(b2, n);
    bn_finalize<1><<<1, 128>>>(g2, be2, inv_n);

    apply_out<<<out_b, 256>>>(a2, (float*)d_out, n);
}